// round 1
// baseline (speedup 1.0000x reference)
#include <cuda_runtime.h>

// Shapes (fixed by the problem)
#define BN 4
#define NN 4096
#define CC 256
#define DD 32
#define OUT_E (4*64*64*256)        // 4194304
// ATT elements = 4*4096*4096 = 67108864

// Scratch (device globals -> no allocations in kernel_launch)
__device__ float g_q[BN * NN * DD];
__device__ float g_k[BN * NN * DD];
__device__ float g_v[BN * NN * CC];
__device__ float g_m[BN * NN];
__device__ float g_s[BN * NN];
__device__ float g_e[67108864];    // raw energy scratch, 256 MB

// ---------------------------------------------------------------------------
// Kernel 1: q = x@Wq + bq, k = x@Wk + bk     (blockIdx.y: 0=q, 1=k)
// block: 64 rows x 32 cols, 256 threads (8 row-groups x 32 lanes)
// ---------------------------------------------------------------------------
__global__ void __launch_bounds__(256) qk_kernel(
    const float* __restrict__ x,
    const float* __restrict__ Wq, const float* __restrict__ bq,
    const float* __restrict__ Wk, const float* __restrict__ bk)
{
    const float* W    = (blockIdx.y == 0) ? Wq : Wk;
    const float* bias = (blockIdx.y == 0) ? bq : bk;
    float* out        = (blockIdx.y == 0) ? g_q : g_k;

    int row0 = blockIdx.x * 64;     // global row in [0, B*N)
    int tid  = threadIdx.x;
    int lane = tid & 31;            // output col d
    int rg   = tid >> 5;            // row group 0..7

    __shared__ __align__(16) float xs[64][68];
    __shared__ float ws[64][33];

    float acc[8];
#pragma unroll
    for (int r = 0; r < 8; r++) acc[r] = 0.f;

    for (int kc = 0; kc < CC; kc += 64) {
        __syncthreads();
#pragma unroll
        for (int p = 0; p < 16; p++) {
            int idx = tid + p * 256;
            int r = idx >> 6, kk = idx & 63;
            xs[r][kk] = x[(long)(row0 + r) * CC + kc + kk];
        }
#pragma unroll
        for (int p = 0; p < 8; p++) {
            int idx = tid + p * 256;
            int kk = idx >> 5, d = idx & 31;
            ws[kk][d] = W[(kc + kk) * DD + d];
        }
        __syncthreads();
#pragma unroll
        for (int k4 = 0; k4 < 16; k4++) {
            float4 a4[8];
#pragma unroll
            for (int r = 0; r < 8; r++)
                a4[r] = *(const float4*)&xs[rg * 8 + r][k4 * 4];
#pragma unroll
            for (int qq = 0; qq < 4; qq++) {
                float bvv = ws[k4 * 4 + qq][lane];
#pragma unroll
                for (int r = 0; r < 8; r++)
                    acc[r] += ((const float*)&a4[r])[qq] * bvv;
            }
        }
    }
    float bb = bias[lane];
#pragma unroll
    for (int r = 0; r < 8; r++)
        out[(long)(row0 + rg * 8 + r) * DD + lane] = acc[r] + bb;
}

// ---------------------------------------------------------------------------
// Kernel 2: v = x@Wv + bv   (64 rows x 256 cols per block, 256 threads)
// thread (warp, lane): rows warp*8..+7, cols {lane*4..+3, 128+lane*4..+3}
// ---------------------------------------------------------------------------
__global__ void __launch_bounds__(256, 2) v_kernel(
    const float* __restrict__ x,
    const float* __restrict__ Wv, const float* __restrict__ bv)
{
    int row0 = blockIdx.x * 64;
    int tid  = threadIdx.x;
    int lane = tid & 31, warp = tid >> 5;

    __shared__ __align__(16) float as_[64][36];
    __shared__ __align__(16) float bs[32][260];

    float acc[8][8];
#pragma unroll
    for (int r = 0; r < 8; r++)
#pragma unroll
        for (int c = 0; c < 8; c++) acc[r][c] = 0.f;

    for (int kc = 0; kc < CC; kc += 32) {
        __syncthreads();
#pragma unroll
        for (int rr = 0; rr < 8; rr++) {
            int r = warp * 8 + rr;
            as_[r][lane] = x[(long)(row0 + r) * CC + kc + lane];
        }
#pragma unroll
        for (int p = 0; p < 8; p++) {
            int idx = tid + p * 256;          // float4 index over 32x256 tile
            int r = idx >> 6, c4 = idx & 63;
            *(float4*)&bs[r][c4 * 4] = *(const float4*)&Wv[(long)(kc + r) * CC + c4 * 4];
        }
        __syncthreads();
#pragma unroll
        for (int k4 = 0; k4 < 8; k4++) {
            float4 a4[8];
#pragma unroll
            for (int r = 0; r < 8; r++)
                a4[r] = *(const float4*)&as_[warp * 8 + r][k4 * 4];
#pragma unroll
            for (int qq = 0; qq < 4; qq++) {
                int kk = k4 * 4 + qq;
                float bvv[8];
                *(float4*)&bvv[0] = *(const float4*)&bs[kk][lane * 4];
                *(float4*)&bvv[4] = *(const float4*)&bs[kk][128 + lane * 4];
#pragma unroll
                for (int r = 0; r < 8; r++) {
                    float av = ((const float*)&a4[r])[qq];
#pragma unroll
                    for (int c = 0; c < 8; c++)
                        acc[r][c] += av * bvv[c];
                }
            }
        }
    }
#pragma unroll
    for (int r = 0; r < 8; r++) {
        int row = row0 + warp * 8 + r;
#pragma unroll
        for (int h = 0; h < 2; h++) {
            int c0 = h * 128 + lane * 4;
            float4 bb = *(const float4*)&bv[c0];
            float4 o;
            o.x = acc[r][h * 4 + 0] + bb.x;
            o.y = acc[r][h * 4 + 1] + bb.y;
            o.z = acc[r][h * 4 + 2] + bb.z;
            o.w = acc[r][h * 4 + 3] + bb.w;
            *(float4*)&g_v[(long)row * CC + c0] = o;
        }
    }
}

// ---------------------------------------------------------------------------
// Kernel 3: energy[b,i,j] = q_i . k_j  + online row max / exp-sum (flash stats)
// block: 64 rows, loops over all 4096 j in 64-col tiles. 256 threads (16x16),
// thread (ty,tx): rows ty*4..+3, cols tx*4..+3 of each tile.
// smem tiles stored d-major: qs[d][row], ks[d][col].
// ---------------------------------------------------------------------------
__global__ void __launch_bounds__(256) energy_kernel()
{
    int b  = blockIdx.y;
    int i0 = blockIdx.x * 64;
    int tid = threadIdx.x;
    int ty = tid >> 4, tx = tid & 15;
    int lane = tid & 31, warp = tid >> 5;

    __shared__ __align__(16) float qs[DD][68];
    __shared__ __align__(16) float ks[DD][68];

    const float* qb = g_q + ((long)b * NN + i0) * DD;
    const float* kb = g_k + (long)b * NN * DD;
    float* eb = g_e + ((long)b * NN + i0) * NN;

    // load q tile transposed: qs[d][row]
#pragma unroll
    for (int rr = 0; rr < 8; rr++) {
        int r = warp * 8 + rr;
        qs[lane][r] = qb[r * DD + lane];
    }

    float m_run[4], s_run[4];
#pragma unroll
    for (int r = 0; r < 4; r++) { m_run[r] = -1e30f; s_run[r] = 0.f; }

    for (int j0 = 0; j0 < NN; j0 += 64) {
        __syncthreads();
#pragma unroll
        for (int rr = 0; rr < 8; rr++) {
            int r = warp * 8 + rr;
            ks[lane][r] = kb[(j0 + r) * DD + lane];
        }
        __syncthreads();

        float acc[4][4];
#pragma unroll
        for (int r = 0; r < 4; r++)
#pragma unroll
            for (int c = 0; c < 4; c++) acc[r][c] = 0.f;

#pragma unroll
        for (int d = 0; d < DD; d++) {
            float4 a4 = *(const float4*)&qs[d][ty * 4];
            float4 b4 = *(const float4*)&ks[d][tx * 4];
            const float* ap = (const float*)&a4;
            const float* bp = (const float*)&b4;
#pragma unroll
            for (int r = 0; r < 4; r++)
#pragma unroll
                for (int c = 0; c < 4; c++)
                    acc[r][c] += ap[r] * bp[c];
        }

        // online stats per row (reduce across the 16 tx lanes; lane = (ty&1)*16+tx
        // so xor masks 1,2,4,8 stay within the tx group)
#pragma unroll
        for (int r = 0; r < 4; r++) {
            float tmax = fmaxf(fmaxf(acc[r][0], acc[r][1]), fmaxf(acc[r][2], acc[r][3]));
#pragma unroll
            for (int msk = 1; msk < 16; msk <<= 1)
                tmax = fmaxf(tmax, __shfl_xor_sync(0xffffffffu, tmax, msk));
            float m_new = fmaxf(m_run[r], tmax);
            float lsum = __expf(acc[r][0] - m_new) + __expf(acc[r][1] - m_new)
                       + __expf(acc[r][2] - m_new) + __expf(acc[r][3] - m_new);
#pragma unroll
            for (int msk = 1; msk < 16; msk <<= 1)
                lsum += __shfl_xor_sync(0xffffffffu, lsum, msk);
            s_run[r] = s_run[r] * __expf(m_run[r] - m_new) + lsum;
            m_run[r] = m_new;
        }

        // store raw energy tile
#pragma unroll
        for (int r = 0; r < 4; r++) {
            float4 o;
            o.x = acc[r][0]; o.y = acc[r][1]; o.z = acc[r][2]; o.w = acc[r][3];
            *(float4*)&eb[(ty * 4 + r) * NN + j0 + tx * 4] = o;
        }
    }

    if (tx == 0) {
#pragma unroll
        for (int r = 0; r < 4; r++) {
            g_m[b * NN + i0 + ty * 4 + r] = m_run[r];
            g_s[b * NN + i0 + ty * 4 + r] = s_run[r];
        }
    }
}

// ---------------------------------------------------------------------------
// Kernel 4: att = exp(e - m)/s (written to att_out if non-null),
//           out = att @ v,  y = out*gamma + x
// block: 64 rows x full C=256 cols. 256 threads; thread (warp,lane):
// rows warp*8..+7, cols {lane*4..+3, 128+lane*4..+3}. j tiled by 32.
// ---------------------------------------------------------------------------
__global__ void __launch_bounds__(256, 2) av_kernel(
    const float* __restrict__ x, const float* __restrict__ gamma,
    float* __restrict__ att_out, float* __restrict__ y)
{
    int b  = blockIdx.y;
    int i0 = blockIdx.x * 64;
    int tid = threadIdx.x;
    int lane = tid & 31, warp = tid >> 5;

    __shared__ __align__(16) float as_[64][36];   // att tile [row][kk]
    __shared__ __align__(16) float vs[32][260];   // v tile [kk][c]
    __shared__ float ms[64], ss[64];

    if (tid < 64) {
        ms[tid] = g_m[b * NN + i0 + tid];
        ss[tid] = 1.0f / g_s[b * NN + i0 + tid];
    }

    float acc[8][8];
#pragma unroll
    for (int r = 0; r < 8; r++)
#pragma unroll
        for (int c = 0; c < 8; c++) acc[r][c] = 0.f;

    const float* eb = g_e + ((long)b * NN + i0) * NN;
    float* ab = att_out ? att_out + ((long)b * NN + i0) * NN : (float*)0;
    const float* vb = g_v + (long)b * NN * CC;

    for (int j0 = 0; j0 < NN; j0 += 32) {
        __syncthreads();
        // attention tile: re-exponentiate energy, write normalized att out
#pragma unroll
        for (int rr = 0; rr < 8; rr++) {
            int r = warp * 8 + rr;
            float e = eb[r * NN + j0 + lane];
            float a = __expf(e - ms[r]) * ss[r];
            as_[r][lane] = a;
            if (ab) ab[r * NN + j0 + lane] = a;
        }
        // v tile 32x256
#pragma unroll
        for (int p = 0; p < 8; p++) {
            int idx = tid + p * 256;
            int r = idx >> 6, c4 = idx & 63;
            *(float4*)&vs[r][c4 * 4] = *(const float4*)&vb[(j0 + r) * CC + c4 * 4];
        }
        __syncthreads();

#pragma unroll
        for (int k4 = 0; k4 < 8; k4++) {
            float4 a4[8];
#pragma unroll
            for (int r = 0; r < 8; r++)
                a4[r] = *(const float4*)&as_[warp * 8 + r][k4 * 4];
#pragma unroll
            for (int qq = 0; qq < 4; qq++) {
                int kk = k4 * 4 + qq;
                float bvv[8];
                *(float4*)&bvv[0] = *(const float4*)&vs[kk][lane * 4];
                *(float4*)&bvv[4] = *(const float4*)&vs[kk][128 + lane * 4];
#pragma unroll
                for (int r = 0; r < 8; r++) {
                    float av = ((const float*)&a4[r])[qq];
#pragma unroll
                    for (int c = 0; c < 8; c++)
                        acc[r][c] += av * bvv[c];
                }
            }
        }
    }

    // epilogue: y = acc*gamma + x
    float g = gamma[0];
    const float* xb = x + ((long)b * NN + i0) * CC;
    float* yb = y + ((long)b * NN + i0) * CC;
#pragma unroll
    for (int r = 0; r < 8; r++) {
        int row = warp * 8 + r;
#pragma unroll
        for (int h = 0; h < 2; h++) {
            int c0 = h * 128 + lane * 4;
            float4 xv = *(const float4*)&xb[row * CC + c0];
            float4 o;
            o.x = acc[r][h * 4 + 0] * g + xv.x;
            o.y = acc[r][h * 4 + 1] * g + xv.y;
            o.z = acc[r][h * 4 + 2] * g + xv.z;
            o.w = acc[r][h * 4 + 3] * g + xv.w;
            *(float4*)&yb[row * CC + c0] = o;
        }
    }
}

// ---------------------------------------------------------------------------
extern "C" void kernel_launch(void* const* d_in, const int* in_sizes, int n_in,
                              void* d_out, int out_size)
{
    const float* x     = (const float*)d_in[0];
    const float* Wq    = (const float*)d_in[1];
    const float* bq    = (const float*)d_in[2];
    const float* Wk    = (const float*)d_in[3];
    const float* bk    = (const float*)d_in[4];
    const float* Wv    = (const float*)d_in[5];
    const float* bv    = (const float*)d_in[6];
    const float* gamma = (const float*)d_in[7];
    float* y = (float*)d_out;

    // Reference returns (out, attention). If the harness buffer holds both,
    // attention follows out; otherwise only out is checked.
    const long ATT_E = (long)BN * NN * NN;   // 67108864
    float* att_out = 0;
    if ((long)out_size == (long)OUT_E + ATT_E) att_out = y + OUT_E;

    qk_kernel<<<dim3(BN * NN / 64, 2), 256>>>(x, Wq, bq, Wk, bk);
    v_kernel<<<BN * NN / 64, 256>>>(x, Wv, bv);
    energy_kernel<<<dim3(NN / 64, BN), 256>>>();
    av_kernel<<<dim3(NN / 64, BN), 256>>>(x, gamma, att_out, y);
}

// round 2
// speedup vs baseline: 2.6168x; 2.6168x over previous
#include <cuda_runtime.h>
#include <cstdint>

#define BN 4
#define NN 4096
#define CC 256
#define DD 32
#define OUT_E (4*64*64*256)

// Scratch (device globals -> no allocations)
__device__ float g_q [BN * NN * DD];
__device__ float g_k [BN * NN * DD];
__device__ float g_vt[(long)BN * CC * NN];   // V transposed: [b][c][j]

// ---------------------------------------------------------------------------
// PTX helpers: ldmatrix (b16 trick on fp32 tiles) + tf32 mma
// ---------------------------------------------------------------------------
__device__ __forceinline__ uint32_t smem_u32(const void* p) {
    return (uint32_t)__cvta_generic_to_shared(p);
}
__device__ __forceinline__ void ldsm4(uint32_t* r, uint32_t addr) {
    asm volatile("ldmatrix.sync.aligned.m8n8.x4.shared.b16 {%0,%1,%2,%3}, [%4];"
                 : "=r"(r[0]), "=r"(r[1]), "=r"(r[2]), "=r"(r[3]) : "r"(addr));
}
__device__ __forceinline__ void ldsm2(uint32_t& r0, uint32_t& r1, uint32_t addr) {
    asm volatile("ldmatrix.sync.aligned.m8n8.x2.shared.b16 {%0,%1}, [%2];"
                 : "=r"(r0), "=r"(r1) : "r"(addr));
}
__device__ __forceinline__ void mma_tf32(float* c, const uint32_t* a, uint32_t b0, uint32_t b1) {
    asm volatile("mma.sync.aligned.m16n8k8.row.col.f32.tf32.tf32.f32 "
                 "{%0,%1,%2,%3}, {%4,%5,%6,%7}, {%8,%9}, {%0,%1,%2,%3};"
                 : "+f"(c[0]), "+f"(c[1]), "+f"(c[2]), "+f"(c[3])
                 : "r"(a[0]), "r"(a[1]), "r"(a[2]), "r"(a[3]), "r"(b0), "r"(b1));
}

// ---------------------------------------------------------------------------
// Kernel 1: q = x@Wq + bq, k = x@Wk + bk   (blockIdx.y: 0=q, 1=k)  [FFMA, small]
// ---------------------------------------------------------------------------
__global__ void __launch_bounds__(256) qk_kernel(
    const float* __restrict__ x,
    const float* __restrict__ Wq, const float* __restrict__ bq,
    const float* __restrict__ Wk, const float* __restrict__ bk)
{
    const float* W    = (blockIdx.y == 0) ? Wq : Wk;
    const float* bias = (blockIdx.y == 0) ? bq : bk;
    float* out        = (blockIdx.y == 0) ? g_q : g_k;

    int row0 = blockIdx.x * 64;
    int tid  = threadIdx.x;
    int lane = tid & 31;
    int rg   = tid >> 5;

    __shared__ __align__(16) float xs[64][68];
    __shared__ float ws[64][33];

    float acc[8];
#pragma unroll
    for (int r = 0; r < 8; r++) acc[r] = 0.f;

    for (int kc = 0; kc < CC; kc += 64) {
        __syncthreads();
#pragma unroll
        for (int p = 0; p < 16; p++) {
            int idx = tid + p * 256;
            int r = idx >> 6, kk = idx & 63;
            xs[r][kk] = x[(long)(row0 + r) * CC + kc + kk];
        }
#pragma unroll
        for (int p = 0; p < 8; p++) {
            int idx = tid + p * 256;
            int kk = idx >> 5, d = idx & 31;
            ws[kk][d] = W[(kc + kk) * DD + d];
        }
        __syncthreads();
#pragma unroll
        for (int k4 = 0; k4 < 16; k4++) {
            float4 a4[8];
#pragma unroll
            for (int r = 0; r < 8; r++)
                a4[r] = *(const float4*)&xs[rg * 8 + r][k4 * 4];
#pragma unroll
            for (int qq = 0; qq < 4; qq++) {
                float bvv = ws[k4 * 4 + qq][lane];
#pragma unroll
                for (int r = 0; r < 8; r++)
                    acc[r] += ((const float*)&a4[r])[qq] * bvv;
            }
        }
    }
    float bb = bias[lane];
#pragma unroll
    for (int r = 0; r < 8; r++)
        out[(long)(row0 + rg * 8 + r) * DD + lane] = acc[r] + bb;
}

// ---------------------------------------------------------------------------
// Kernel 2: v = x@Wv + bv, stored TRANSPOSED to g_vt[b][c][j]
// ---------------------------------------------------------------------------
__global__ void __launch_bounds__(256, 2) v_kernel(
    const float* __restrict__ x,
    const float* __restrict__ Wv, const float* __restrict__ bv)
{
    int row0 = blockIdx.x * 64;
    int tid  = threadIdx.x;
    int lane = tid & 31, warp = tid >> 5;

    __shared__ __align__(16) float as_[64][36];
    __shared__ __align__(16) float bs[32][260];

    float acc[8][8];
#pragma unroll
    for (int r = 0; r < 8; r++)
#pragma unroll
        for (int c = 0; c < 8; c++) acc[r][c] = 0.f;

    for (int kc = 0; kc < CC; kc += 32) {
        __syncthreads();
#pragma unroll
        for (int rr = 0; rr < 8; rr++) {
            int r = warp * 8 + rr;
            as_[r][lane] = x[(long)(row0 + r) * CC + kc + lane];
        }
#pragma unroll
        for (int p = 0; p < 8; p++) {
            int idx = tid + p * 256;
            int r = idx >> 6, c4 = idx & 63;
            *(float4*)&bs[r][c4 * 4] = *(const float4*)&Wv[(long)(kc + r) * CC + c4 * 4];
        }
        __syncthreads();
#pragma unroll
        for (int k4 = 0; k4 < 8; k4++) {
            float4 a4[8];
#pragma unroll
            for (int r = 0; r < 8; r++)
                a4[r] = *(const float4*)&as_[warp * 8 + r][k4 * 4];
#pragma unroll
            for (int qq = 0; qq < 4; qq++) {
                int kk = k4 * 4 + qq;
                float bvv[8];
                *(float4*)&bvv[0] = *(const float4*)&bs[kk][lane * 4];
                *(float4*)&bvv[4] = *(const float4*)&bs[kk][128 + lane * 4];
#pragma unroll
                for (int r = 0; r < 8; r++) {
                    float av = ((const float*)&a4[r])[qq];
#pragma unroll
                    for (int c = 0; c < 8; c++)
                        acc[r][c] += av * bvv[c];
                }
            }
        }
    }
    // transposed epilogue: thread holds 8 consecutive j-rows x 8 c-cols
    int rowg = row0 + warp * 8;
    int bb   = rowg / NN;
    int jj   = rowg % NN;
    float* vt = g_vt + (long)bb * CC * NN;
#pragma unroll
    for (int h = 0; h < 2; h++) {
#pragma unroll
        for (int cc = 0; cc < 4; cc++) {
            int c = h * 128 + lane * 4 + cc;
            float bias = bv[c];
            int idx = h * 4 + cc;
            float4 p0, p1;
            p0.x = acc[0][idx] + bias; p0.y = acc[1][idx] + bias;
            p0.z = acc[2][idx] + bias; p0.w = acc[3][idx] + bias;
            p1.x = acc[4][idx] + bias; p1.y = acc[5][idx] + bias;
            p1.z = acc[6][idx] + bias; p1.w = acc[7][idx] + bias;
            *(float4*)&vt[(long)c * NN + jj]     = p0;
            *(float4*)&vt[(long)c * NN + jj + 4] = p1;
        }
    }
}

// ---------------------------------------------------------------------------
// Kernel 3: fused attention. Per block: 64 i-rows of one batch.
//  pass 1: s_i = sum_j exp(q_i.k_j)      (tf32 mma, JT=64)
//  pass 2: att = exp(e)/s -> gmem; out += att @ v (tf32 mma, JT=16)
//  epilogue: y = out*gamma + x
// Warp layout: energy (4x2): wm=i-band(16), wn=j-slice; AV (2x4): am=32 rows, an=64 cols
// ---------------------------------------------------------------------------
__global__ void __launch_bounds__(256, 2) attn_kernel(
    const float* __restrict__ x, const float* __restrict__ gamma,
    float* __restrict__ att_out, float* __restrict__ y)
{
    int b   = blockIdx.y;
    int i0  = blockIdx.x * 64;
    int tid = threadIdx.x;
    int lane = tid & 31, w = tid >> 5;
    int wm = w & 3, wn = w >> 2;          // energy partition
    int am = w & 1, an = w >> 1;          // AV partition
    int grp = lane >> 3, lr = lane & 7;

    // sbuf overlays: q staging [64][36] / pass1 K tile [64][36] / pass2 V^T tile [256][20]
    __shared__ __align__(16) float sbuf[5120];
    __shared__ __align__(16) float as_[64][20];   // att tile (fp32)
    __shared__ __align__(16) float ks2[16][36];   // pass2 K tile
    __shared__ float sred[64][8];
    __shared__ float ss[64];

    uint32_t sbuf_b = smem_u32(sbuf);
    uint32_t as_b   = smem_u32(&as_[0][0]);
    uint32_t ks2_b  = smem_u32(&ks2[0][0]);

    const float* qg = g_q + ((long)b * NN + i0) * DD;
    const float* kg = g_k + (long)b * NN * DD;
    const float* vtg = g_vt + (long)b * CC * NN;

    // ---- stage q tile into sbuf (stride 36) and preload A fragments ----
#pragma unroll
    for (int p = 0; p < 2; p++) {
        int idx = tid + p * 256;
        int r = idx >> 3, c4 = idx & 7;
        *(float4*)&sbuf[r * 36 + c4 * 4] = *(const float4*)&qg[r * DD + c4 * 4];
    }
    __syncthreads();
    uint32_t qf[4][4];
    {
        uint32_t qb = sbuf_b + (((wm * 16 + (grp & 1) * 8 + lr) * 36 + ((grp >> 1) << 2)) << 2);
#pragma unroll
        for (int k = 0; k < 4; k++) ldsm4(qf[k], qb + k * 32);
    }
    if (tid < 64) ss[tid] = 0.f;

    // =========================== PASS 1: row sums ==========================
    float s0 = 0.f, s1 = 0.f;
    uint32_t ks1b = sbuf_b + (((wn * 32 + (grp >> 1) * 8 + lr) * 36 + ((grp & 1) << 2)) << 2);
    for (int j0 = 0; j0 < NN; j0 += 64) {
        __syncthreads();
#pragma unroll
        for (int p = 0; p < 2; p++) {
            int idx = tid + p * 256;
            int r = idx >> 3, c4 = idx & 7;
            *(float4*)&sbuf[r * 36 + c4 * 4] = *(const float4*)&kg[(j0 + r) * DD + c4 * 4];
        }
        __syncthreads();
#pragma unroll
        for (int p = 0; p < 2; p++) {
            float c0[4] = {0.f,0.f,0.f,0.f}, c1[4] = {0.f,0.f,0.f,0.f};
#pragma unroll
            for (int k = 0; k < 4; k++) {
                uint32_t bfr[4];
                ldsm4(bfr, ks1b + p * 2304 + k * 32);   // 16*36*4 = 2304
                mma_tf32(c0, qf[k], bfr[0], bfr[1]);
                mma_tf32(c1, qf[k], bfr[2], bfr[3]);
            }
            s0 += __expf(c0[0]) + __expf(c0[1]) + __expf(c1[0]) + __expf(c1[1]);
            s1 += __expf(c0[2]) + __expf(c0[3]) + __expf(c1[2]) + __expf(c1[3]);
        }
    }
    // deterministic reduction: 8 partials per row
    {
        int r0 = wm * 16 + (lane >> 2);
        int sl = wn * 4 + (lane & 3);
        sred[r0][sl]     = s0;
        sred[r0 + 8][sl] = s1;
    }
    __syncthreads();
    if (tid < 64) {
        float t = 0.f;
#pragma unroll
        for (int i = 0; i < 8; i++) t += sred[tid][i];
        ss[tid] = 1.0f / t;
    }
    __syncthreads();
    float is0 = ss[wm * 16 + (lane >> 2)];
    float is1 = ss[wm * 16 + (lane >> 2) + 8];

    // =========================== PASS 2: att + AV ==========================
    float Cv[2][8][4];
#pragma unroll
    for (int mi = 0; mi < 2; mi++)
#pragma unroll
        for (int ni = 0; ni < 8; ni++)
#pragma unroll
            for (int u = 0; u < 4; u++) Cv[mi][ni][u] = 0.f;

    float* ab = att_out ? att_out + ((long)b * NN + i0) * NN : (float*)0;
    uint32_t eb  = ks2_b + (((wn * 8 + lr) * 36 + ((grp & 1) << 2)) << 2);
    uint32_t avA = as_b  + (((am * 32 + (grp & 1) * 8 + lr) * 20 + ((grp >> 1) << 2)) << 2);
    uint32_t avB = sbuf_b + (((an * 64 + (grp >> 1) * 8 + lr) * 20 + ((grp & 1) << 2)) << 2);
    int sr = wm * 16 + (lane >> 2);
    int sc = wn * 8 + ((lane & 3) << 1);

    for (int j0 = 0; j0 < NN; j0 += 16) {
        __syncthreads();
        if (tid < 128) {
            int r = tid >> 3, c4 = tid & 7;
            *(float4*)&ks2[r][c4 * 4] = *(const float4*)&kg[(j0 + r) * DD + c4 * 4];
        }
#pragma unroll
        for (int p = 0; p < 4; p++) {
            int idx = tid + p * 256;
            int c = idx >> 2, c4 = idx & 3;
            *(float4*)&sbuf[c * 20 + c4 * 4] = *(const float4*)&vtg[(long)c * NN + j0 + c4 * 4];
        }
        __syncthreads();

        // energy -> att fragment
        float ce[4] = {0.f,0.f,0.f,0.f};
#pragma unroll
        for (int k = 0; k < 4; k++) {
            uint32_t b0, b1;
            ldsm2(b0, b1, eb + k * 32);
            mma_tf32(ce, qf[k], b0, b1);
        }
        float a0 = __expf(ce[0]) * is0, a1 = __expf(ce[1]) * is0;
        float a2 = __expf(ce[2]) * is1, a3 = __expf(ce[3]) * is1;
        *(float2*)&as_[sr][sc]     = make_float2(a0, a1);
        *(float2*)&as_[sr + 8][sc] = make_float2(a2, a3);
        __syncthreads();

        // attention output (exact fp32)
        if (ab) {
            int r = tid >> 2, c4 = tid & 3;
            *(float4*)&ab[(long)r * NN + j0 + c4 * 4] = *(const float4*)&as_[r][c4 * 4];
        }

        // AV mma: k = 2 steps of 8 over the 16 j's
#pragma unroll
        for (int k = 0; k < 2; k++) {
            uint32_t A0[4], A1[4];
            ldsm4(A0, avA + k * 32);
            ldsm4(A1, avA + 1280 + k * 32);           // +16 rows (16*20*4)
#pragma unroll
            for (int ntp = 0; ntp < 4; ntp++) {
                uint32_t Bv[4];
                ldsm4(Bv, avB + ntp * 1280 + k * 32); // +16 c-rows per pair
                mma_tf32(Cv[0][ntp * 2],     A0, Bv[0], Bv[1]);
                mma_tf32(Cv[0][ntp * 2 + 1], A0, Bv[2], Bv[3]);
                mma_tf32(Cv[1][ntp * 2],     A1, Bv[0], Bv[1]);
                mma_tf32(Cv[1][ntp * 2 + 1], A1, Bv[2], Bv[3]);
            }
        }
    }

    // ---- epilogue: y = Cv*gamma + x ----
    float g = gamma[0];
    const float* xb = x + ((long)b * NN + i0) * CC;
    float* yb = y + ((long)b * NN + i0) * CC;
#pragma unroll
    for (int mi = 0; mi < 2; mi++) {
#pragma unroll
        for (int ni = 0; ni < 8; ni++) {
            int r0 = am * 32 + mi * 16 + (lane >> 2);
            int c  = an * 64 + ni * 8 + ((lane & 3) << 1);
            float2 x0 = *(const float2*)&xb[r0 * CC + c];
            float2 x1 = *(const float2*)&xb[(r0 + 8) * CC + c];
            float2 o0, o1;
            o0.x = Cv[mi][ni][0] * g + x0.x;  o0.y = Cv[mi][ni][1] * g + x0.y;
            o1.x = Cv[mi][ni][2] * g + x1.x;  o1.y = Cv[mi][ni][3] * g + x1.y;
            *(float2*)&yb[r0 * CC + c]       = o0;
            *(float2*)&yb[(r0 + 8) * CC + c] = o1;
        }
    }
}

// ---------------------------------------------------------------------------
extern "C" void kernel_launch(void* const* d_in, const int* in_sizes, int n_in,
                              void* d_out, int out_size)
{
    const float* x     = (const float*)d_in[0];
    const float* Wq    = (const float*)d_in[1];
    const float* bq    = (const float*)d_in[2];
    const float* Wk    = (const float*)d_in[3];
    const float* bk    = (const float*)d_in[4];
    const float* Wv    = (const float*)d_in[5];
    const float* bv    = (const float*)d_in[6];
    const float* gamma = (const float*)d_in[7];
    float* y = (float*)d_out;

    const long ATT_E = (long)BN * NN * NN;
    float* att_out = 0;
    if ((long)out_size == (long)OUT_E + ATT_E) att_out = y + OUT_E;

    qk_kernel<<<dim3(BN * NN / 64, 2), 256>>>(x, Wq, bq, Wk, bk);
    v_kernel<<<BN * NN / 64, 256>>>(x, Wv, bv);
    attn_kernel<<<dim3(NN / 64, BN), 256>>>(x, gamma, att_out, y);
}

// round 4
// speedup vs baseline: 5.1757x; 1.9779x over previous
#include <cuda_runtime.h>
#include <cuda_fp16.h>
#include <cstdint>

#define BN 4
#define NN 4096
#define CC 256
#define DD 32
#define OUT_E (4*64*64*256)

// Scratch (device globals -> no allocations)
__device__ __half g_qh [BN * NN * DD];
__device__ __half g_kh [BN * NN * DD];
__device__ __half g_vth[(long)BN * CC * NN];   // V transposed: [b][c][j], fp16

// ---------------------------------------------------------------------------
// helpers
// ---------------------------------------------------------------------------
__device__ __forceinline__ uint32_t smem_u32(const void* p) {
    return (uint32_t)__cvta_generic_to_shared(p);
}
__device__ __forceinline__ void ldsm4(uint32_t* r, uint32_t addr) {
    asm volatile("ldmatrix.sync.aligned.m8n8.x4.shared.b16 {%0,%1,%2,%3}, [%4];"
                 : "=r"(r[0]), "=r"(r[1]), "=r"(r[2]), "=r"(r[3]) : "r"(addr));
}
__device__ __forceinline__ void mma_f16(float* c, const uint32_t* a,
                                        uint32_t b0, uint32_t b1) {
    asm volatile("mma.sync.aligned.m16n8k16.row.col.f32.f16.f16.f32 "
                 "{%0,%1,%2,%3}, {%4,%5,%6,%7}, {%8,%9}, {%0,%1,%2,%3};"
                 : "+f"(c[0]), "+f"(c[1]), "+f"(c[2]), "+f"(c[3])
                 : "r"(a[0]), "r"(a[1]), "r"(a[2]), "r"(a[3]), "r"(b0), "r"(b1));
}
#define CP16(dst, src) \
    asm volatile("cp.async.cg.shared.global [%0], [%1], 16;" :: "r"(dst), "l"(src))
#define CP_COMMIT() asm volatile("cp.async.commit_group;" ::: "memory")
#define CP_WAIT(n)  asm volatile("cp.async.wait_group %0;" :: "n"(n) : "memory")

// smem layout (bytes). Rows padded to 80B (40 halves) -> conflict-free ldmatrix.
#define Q_OFF     0        // 64 x 32 half          (5120)
#define P_OFF     5120     // 64 x 32 half          (5120)
#define K2_OFF    10240    // 3 stages x 32x32 half (7680)
#define V_OFF     17920    // 3 stages x 256x32 half(61440); pass1 K1 stages live here
#define SRED_OFF  79360    // 64 x 2 f32            (512)
#define SS_OFF    79872    // 64 f32                (256)
#define SMEM_ATTN 80128
#define K1_STAGE  10240    // 128 rows x 80B
#define V_STAGE   20480    // 256 rows x 80B
#define K2_STAGE  2560     // 32 rows x 80B

// ---------------------------------------------------------------------------
// Kernel 1: fused q & k projections -> fp16
// block: 64 rows; 256 thr (8 row-groups x 32 lanes)
// ---------------------------------------------------------------------------
__global__ void __launch_bounds__(256) qkf_kernel(
    const float* __restrict__ x,
    const float* __restrict__ Wq, const float* __restrict__ bq,
    const float* __restrict__ Wk, const float* __restrict__ bk)
{
    int row0 = blockIdx.x * 64;
    int tid  = threadIdx.x;
    int lane = tid & 31;
    int rg   = tid >> 5;

    __shared__ __align__(16) float xs[64][68];
    __shared__ float wsq[64][33];
    __shared__ float wsk[64][33];

    float aq[8], ak[8];
#pragma unroll
    for (int r = 0; r < 8; r++) { aq[r] = 0.f; ak[r] = 0.f; }

    for (int kc = 0; kc < CC; kc += 64) {
        __syncthreads();
#pragma unroll
        for (int p = 0; p < 16; p++) {
            int idx = tid + p * 256;
            int r = idx >> 6, kk = idx & 63;
            xs[r][kk] = x[(long)(row0 + r) * CC + kc + kk];
        }
#pragma unroll
        for (int p = 0; p < 8; p++) {
            int idx = tid + p * 256;
            int kk = idx >> 5, d = idx & 31;
            wsq[kk][d] = Wq[(kc + kk) * DD + d];
            wsk[kk][d] = Wk[(kc + kk) * DD + d];
        }
        __syncthreads();
#pragma unroll
        for (int k4 = 0; k4 < 16; k4++) {
            float4 a4[8];
#pragma unroll
            for (int r = 0; r < 8; r++)
                a4[r] = *(const float4*)&xs[rg * 8 + r][k4 * 4];
#pragma unroll
            for (int qq = 0; qq < 4; qq++) {
                float bvq = wsq[k4 * 4 + qq][lane];
                float bvk = wsk[k4 * 4 + qq][lane];
#pragma unroll
                for (int r = 0; r < 8; r++) {
                    float av = ((const float*)&a4[r])[qq];
                    aq[r] += av * bvq;
                    ak[r] += av * bvk;
                }
            }
        }
    }
    float bbq = bq[lane], bbk = bk[lane];
#pragma unroll
    for (int r = 0; r < 8; r++) {
        long o = (long)(row0 + rg * 8 + r) * DD + lane;
        g_qh[o] = __float2half_rn(aq[r] + bbq);
        g_kh[o] = __float2half_rn(ak[r] + bbk);
    }
}

// ---------------------------------------------------------------------------
// Kernel 2: v = x@Wv + bv, TRANSPOSED fp16 to g_vth[b][c][j]
// ---------------------------------------------------------------------------
__global__ void __launch_bounds__(256, 2) v_kernel(
    const float* __restrict__ x,
    const float* __restrict__ Wv, const float* __restrict__ bv)
{
    int row0 = blockIdx.x * 64;
    int tid  = threadIdx.x;
    int lane = tid & 31, warp = tid >> 5;

    __shared__ __align__(16) float as_[64][36];
    __shared__ __align__(16) float bs[32][260];

    float acc[8][8];
#pragma unroll
    for (int r = 0; r < 8; r++)
#pragma unroll
        for (int c = 0; c < 8; c++) acc[r][c] = 0.f;

    for (int kc = 0; kc < CC; kc += 32) {
        __syncthreads();
#pragma unroll
        for (int rr = 0; rr < 8; rr++) {
            int r = warp * 8 + rr;
            as_[r][lane] = x[(long)(row0 + r) * CC + kc + lane];
        }
#pragma unroll
        for (int p = 0; p < 8; p++) {
            int idx = tid + p * 256;
            int r = idx >> 6, c4 = idx & 63;
            *(float4*)&bs[r][c4 * 4] = *(const float4*)&Wv[(long)(kc + r) * CC + c4 * 4];
        }
        __syncthreads();
#pragma unroll
        for (int k4 = 0; k4 < 8; k4++) {
            float4 a4[8];
#pragma unroll
            for (int r = 0; r < 8; r++)
                a4[r] = *(const float4*)&as_[warp * 8 + r][k4 * 4];
#pragma unroll
            for (int qq = 0; qq < 4; qq++) {
                int kk = k4 * 4 + qq;
                float bvv[8];
                *(float4*)&bvv[0] = *(const float4*)&bs[kk][lane * 4];
                *(float4*)&bvv[4] = *(const float4*)&bs[kk][128 + lane * 4];
#pragma unroll
                for (int r = 0; r < 8; r++) {
                    float av = ((const float*)&a4[r])[qq];
#pragma unroll
                    for (int c = 0; c < 8; c++)
                        acc[r][c] += av * bvv[c];
                }
            }
        }
    }
    int rowg = row0 + warp * 8;
    int bb   = rowg / NN;
    int jj   = rowg % NN;
    __half* vt = g_vth + (long)bb * CC * NN;
#pragma unroll
    for (int h = 0; h < 2; h++) {
#pragma unroll
        for (int cc = 0; cc < 4; cc++) {
            int c = h * 128 + lane * 4 + cc;
            float bias = bv[c];
            int idx = h * 4 + cc;
            __half2 pk[4];
            pk[0] = __floats2half2_rn(acc[0][idx] + bias, acc[1][idx] + bias);
            pk[1] = __floats2half2_rn(acc[2][idx] + bias, acc[3][idx] + bias);
            pk[2] = __floats2half2_rn(acc[4][idx] + bias, acc[5][idx] + bias);
            pk[3] = __floats2half2_rn(acc[6][idx] + bias, acc[7][idx] + bias);
            *(uint4*)&vt[(long)c * NN + jj] = *(uint4*)pk;
        }
    }
}

// ---------------------------------------------------------------------------
// Kernel 3: fused attention, fp16 HMMA. 64 i-rows per CTA, grid (64, 4).
//  pass 1: s_i = sum_j exp(q_i.k_j)   JT=128, cp.async 3-stage
//  pass 2: att=exp(e)/s -> gmem(f32); O += P@V  JT=32, cp.async 3-stage
// Warp layouts: E: 4i x 2j (wi,wj); AV: 2i x 4c (avi,avc)
// ---------------------------------------------------------------------------
__global__ void __launch_bounds__(256, 2) attn_kernel(
    const float* __restrict__ x, const float* __restrict__ gamma,
    float* __restrict__ att_out, float* __restrict__ y)
{
    extern __shared__ __align__(16) char smem[];
    const uint32_t sb = smem_u32(smem);
    const int tid  = threadIdx.x;
    const int lane = tid & 31, w = tid >> 5;
    const int wi = w & 3, wj = w >> 2;
    const int avi = w & 1, avc = w >> 1;

    const int b  = blockIdx.y;
    const int i0 = blockIdx.x * 64;

    const __half* qg  = g_qh + ((long)b * NN + i0) * DD;
    const __half* kg  = g_kh + (long)b * NN * DD;
    const __half* vtg = g_vth + (long)b * CC * NN;

    // ---- Q tile -> smem (64 rows x 64B, stride 80B) ----
    {
        int r = tid >> 2, ch = tid & 3;
        *(uint4*)(smem + Q_OFF + r * 80 + ch * 16) =
            *(const uint4*)(qg + r * DD + ch * 8);
    }

    // prefetch K1 stage 0
    {
        uint32_t kst = sb + V_OFF;
#pragma unroll
        for (int p = 0; p < 2; p++) {
            int idx = tid + p * 256;
            int r = idx >> 2, ch = idx & 3;
            CP16(kst + r * 80 + ch * 16, kg + r * DD + ch * 8);
        }
        CP_COMMIT();
    }
    __syncthreads();

    // ---- preload Q fragments (held all kernel) ----
    uint32_t qf[2][4];
    {
        uint32_t base = sb + Q_OFF
            + (wi * 16 + (lane & 7) + ((lane >> 3) & 1) * 8) * 80
            + (lane >> 4) * 16;
        ldsm4(qf[0], base);
        ldsm4(qf[1], base + 32);
    }

    // =========================== PASS 1 ============================
    float s0 = 0.f, s1 = 0.f;
    for (int t = 0; t < 32; t++) {
        if (t + 1 < 32) {
            uint32_t kst = sb + V_OFF + ((t + 1) % 3) * K1_STAGE;
            const __half* src = kg + (t + 1) * 128 * DD;
#pragma unroll
            for (int p = 0; p < 2; p++) {
                int idx = tid + p * 256;
                int r = idx >> 2, ch = idx & 3;
                CP16(kst + r * 80 + ch * 16, src + r * DD + ch * 8);
            }
        }
        CP_COMMIT();
        CP_WAIT(1);
        __syncthreads();

        uint32_t kst = sb + V_OFF + (t % 3) * K1_STAGE;
        uint32_t bbase = kst + (wj * 64 + (lane & 7)) * 80 + (lane >> 3) * 16;
#pragma unroll
        for (int nt = 0; nt < 8; nt++) {
            uint32_t bf[4];
            ldsm4(bf, bbase + nt * 8 * 80);
            float c[4] = {0.f, 0.f, 0.f, 0.f};
            mma_f16(c, qf[0], bf[0], bf[1]);
            mma_f16(c, qf[1], bf[2], bf[3]);
            s0 += __expf(c[0]) + __expf(c[1]);
            s1 += __expf(c[2]) + __expf(c[3]);
        }
        __syncthreads();
    }
    // reduce across lane&3 (4 lanes share a row)
    s0 += __shfl_xor_sync(0xffffffffu, s0, 1);
    s0 += __shfl_xor_sync(0xffffffffu, s0, 2);
    s1 += __shfl_xor_sync(0xffffffffu, s1, 1);
    s1 += __shfl_xor_sync(0xffffffffu, s1, 2);
    {
        float* sred = (float*)(smem + SRED_OFF);
        if ((lane & 3) == 0) {
            int r = wi * 16 + (lane >> 2);
            sred[r * 2 + wj]       = s0;
            sred[(r + 8) * 2 + wj] = s1;
        }
    }
    __syncthreads();
    if (tid < 64) {
        float* sred = (float*)(smem + SRED_OFF);
        ((float*)(smem + SS_OFF))[tid] = 1.0f / (sred[tid * 2] + sred[tid * 2 + 1]);
    }

    // prefetch V+K2 stage 0
    {
        uint32_t vst = sb + V_OFF, k2t = sb + K2_OFF;
#pragma unroll
        for (int p = 0; p < 4; p++) {
            int idx = tid + p * 256;
            int c = idx >> 2, ch = idx & 3;
            CP16(vst + c * 80 + ch * 16, vtg + (long)c * NN + ch * 8);
        }
        if (tid < 128) {
            int r = tid >> 2, ch = tid & 3;
            CP16(k2t + r * 80 + ch * 16, kg + r * DD + ch * 8);
        }
        CP_COMMIT();
    }
    __syncthreads();
    const float is0 = ((const float*)(smem + SS_OFF))[wi * 16 + (lane >> 2)];
    const float is1 = ((const float*)(smem + SS_OFF))[wi * 16 + (lane >> 2) + 8];

    // =========================== PASS 2 ============================
    float acc[2][8][4];
#pragma unroll
    for (int mt = 0; mt < 2; mt++)
#pragma unroll
        for (int nt = 0; nt < 8; nt++)
#pragma unroll
            for (int u = 0; u < 4; u++) acc[mt][nt][u] = 0.f;

    float* ab = att_out ? att_out + ((long)b * NN + i0) * NN : (float*)0;
    const int er0 = wi * 16 + (lane >> 2);
    const int ec  = wj * 16 + ((lane & 3) << 1);

    for (int t = 0; t < 128; t++) {
        const int j0 = t * 32;
        if (t + 1 < 128) {
            uint32_t vst = sb + V_OFF + ((t + 1) % 3) * V_STAGE;
            uint32_t k2t = sb + K2_OFF + ((t + 1) % 3) * K2_STAGE;
            const __half* vsrc = vtg + j0 + 32;
            const __half* ksrc = kg + (j0 + 32) * DD;
#pragma unroll
            for (int p = 0; p < 4; p++) {
                int idx = tid + p * 256;
                int c = idx >> 2, ch = idx & 3;
                CP16(vst + c * 80 + ch * 16, vsrc + (long)c * NN + ch * 8);
            }
            if (tid < 128) {
                int r = tid >> 2, ch = tid & 3;
                CP16(k2t + r * 80 + ch * 16, ksrc + r * DD + ch * 8);
            }
        }
        CP_COMMIT();
        CP_WAIT(1);
        __syncthreads();

        uint32_t vst = sb + V_OFF + (t % 3) * V_STAGE;
        uint32_t k2t = sb + K2_OFF + (t % 3) * K2_STAGE;

        // ---- E (64x32) + exp + P(fp16) + att(f32) ----
        uint32_t ebase = k2t + (wj * 16 + (lane & 7)) * 80 + (lane >> 3) * 16;
#pragma unroll
        for (int nt = 0; nt < 2; nt++) {
            uint32_t bf[4];
            ldsm4(bf, ebase + nt * 8 * 80);
            float c[4] = {0.f, 0.f, 0.f, 0.f};
            mma_f16(c, qf[0], bf[0], bf[1]);
            mma_f16(c, qf[1], bf[2], bf[3]);
            float a0 = __expf(c[0]) * is0, a1 = __expf(c[1]) * is0;
            float a2 = __expf(c[2]) * is1, a3 = __expf(c[3]) * is1;
            int col = ec + nt * 8;
            *(__half2*)(smem + P_OFF + er0 * 80 + col * 2)       = __floats2half2_rn(a0, a1);
            *(__half2*)(smem + P_OFF + (er0 + 8) * 80 + col * 2) = __floats2half2_rn(a2, a3);
            if (ab) {
                *(float2*)&ab[(long)er0 * NN + j0 + col]       = make_float2(a0, a1);
                *(float2*)&ab[(long)(er0 + 8) * NN + j0 + col] = make_float2(a2, a3);
            }
        }
        __syncthreads();

        // ---- AV: O(64x256) += P(64x32) @ V^T(256x32)^T ----
        uint32_t af[2][2][4];
        {
            uint32_t abase = sb + P_OFF
                + (avi * 32 + (lane & 7) + ((lane >> 3) & 1) * 8) * 80
                + (lane >> 4) * 16;
#pragma unroll
            for (int mt = 0; mt < 2; mt++) {
                ldsm4(af[mt][0], abase + mt * 16 * 80);
                ldsm4(af[mt][1], abase + mt * 16 * 80 + 32);
            }
        }
        uint32_t bbase = vst + (avc * 64 + (lane & 7)) * 80 + (lane >> 3) * 16;
#pragma unroll
        for (int nt = 0; nt < 8; nt++) {
            uint32_t bv[4];
            ldsm4(bv, bbase + nt * 8 * 80);
            mma_f16(acc[0][nt], af[0][0], bv[0], bv[1]);
            mma_f16(acc[0][nt], af[0][1], bv[2], bv[3]);
            mma_f16(acc[1][nt], af[1][0], bv[0], bv[1]);
            mma_f16(acc[1][nt], af[1][1], bv[2], bv[3]);
        }
    }

    // ---- epilogue: y = acc*gamma + x ----
    const float g = gamma[0];
    const float* xb = x + ((long)b * NN + i0) * CC;
    float* yb = y + ((long)b * NN + i0) * CC;
#pragma unroll
    for (int mt = 0; mt < 2; mt++) {
        int r0 = avi * 32 + mt * 16 + (lane >> 2);
#pragma unroll
        for (int nt = 0; nt < 8; nt++) {
            int c = avc * 64 + nt * 8 + ((lane & 3) << 1);
            float2 x0 = *(const float2*)&xb[(long)r0 * CC + c];
            float2 x1 = *(const float2*)&xb[(long)(r0 + 8) * CC + c];
            float2 o0, o1;
            o0.x = acc[mt][nt][0] * g + x0.x;  o0.y = acc[mt][nt][1] * g + x0.y;
            o1.x = acc[mt][nt][2] * g + x1.x;  o1.y = acc[mt][nt][3] * g + x1.y;
            *(float2*)&yb[(long)r0 * CC + c]       = o0;
            *(float2*)&yb[(long)(r0 + 8) * CC + c] = o1;
        }
    }
}

// ---------------------------------------------------------------------------
extern "C" void kernel_launch(void* const* d_in, const int* in_sizes, int n_in,
                              void* d_out, int out_size)
{
    const float* x     = (const float*)d_in[0];
    const float* Wq    = (const float*)d_in[1];
    const float* bq    = (const float*)d_in[2];
    const float* Wk    = (const float*)d_in[3];
    const float* bk    = (const float*)d_in[4];
    const float* Wv    = (const float*)d_in[5];
    const float* bv    = (const float*)d_in[6];
    const float* gamma = (const float*)d_in[7];
    float* y = (float*)d_out;

    const long ATT_E = (long)BN * NN * NN;
    float* att_out = 0;
    if ((long)out_size == (long)OUT_E + ATT_E) att_out = y + OUT_E;

    cudaFuncSetAttribute(attn_kernel, cudaFuncAttributeMaxDynamicSharedMemorySize,
                         SMEM_ATTN);

    qkf_kernel<<<BN * NN / 64, 256>>>(x, Wq, bq, Wk, bk);
    v_kernel<<<BN * NN / 64, 256>>>(x, Wv, bv);
    attn_kernel<<<dim3(NN / 64, BN), 256, SMEM_ATTN>>>(x, gamma, att_out, y);
}

// round 5
// speedup vs baseline: 5.2403x; 1.0125x over previous
#include <cuda_runtime.h>
#include <cuda_fp16.h>
#include <cuda_fp8.h>
#include <cstdint>

#define BN 4
#define NN 4096
#define CC 256
#define DD 32
#define OUT_E (4*64*64*256)
#define PSCALE 4096.0f

// Scratch (device globals -> no allocations)
__device__ __half   g_qh [BN * NN * DD];
__device__ __half   g_kh [BN * NN * DD];
__device__ uint8_t  g_v8t[(long)BN * CC * NN];   // V transposed: [b][c][j], e4m3

// ---------------------------------------------------------------------------
// helpers
// ---------------------------------------------------------------------------
__device__ __forceinline__ uint32_t smem_u32(const void* p) {
    return (uint32_t)__cvta_generic_to_shared(p);
}
__device__ __forceinline__ void ldsm4(uint32_t* r, uint32_t addr) {
    asm volatile("ldmatrix.sync.aligned.m8n8.x4.shared.b16 {%0,%1,%2,%3}, [%4];"
                 : "=r"(r[0]), "=r"(r[1]), "=r"(r[2]), "=r"(r[3]) : "r"(addr));
}
__device__ __forceinline__ void mma_f16(float* c, const uint32_t* a,
                                        uint32_t b0, uint32_t b1) {
    asm volatile("mma.sync.aligned.m16n8k16.row.col.f32.f16.f16.f32 "
                 "{%0,%1,%2,%3}, {%4,%5,%6,%7}, {%8,%9}, {%0,%1,%2,%3};"
                 : "+f"(c[0]), "+f"(c[1]), "+f"(c[2]), "+f"(c[3])
                 : "r"(a[0]), "r"(a[1]), "r"(a[2]), "r"(a[3]), "r"(b0), "r"(b1));
}
__device__ __forceinline__ void mma_f8(float* c, const uint32_t* a,
                                       uint32_t b0, uint32_t b1) {
    asm volatile("mma.sync.aligned.m16n8k32.row.col.f32.e4m3.e4m3.f32 "
                 "{%0,%1,%2,%3}, {%4,%5,%6,%7}, {%8,%9}, {%0,%1,%2,%3};"
                 : "+f"(c[0]), "+f"(c[1]), "+f"(c[2]), "+f"(c[3])
                 : "r"(a[0]), "r"(a[1]), "r"(a[2]), "r"(a[3]), "r"(b0), "r"(b1));
}
__device__ __forceinline__ unsigned short f2_to_e4m3x2(float lo, float hi) {
    return (unsigned short)__nv_cvt_float2_to_fp8x2(make_float2(lo, hi),
                                                    __NV_SATFINITE, __NV_E4M3);
}
#define CP16(dst, src) \
    asm volatile("cp.async.cg.shared.global [%0], [%1], 16;" :: "r"(dst), "l"(src))
#define CP_COMMIT() asm volatile("cp.async.commit_group;" ::: "memory")
#define CP_WAIT(n)  asm volatile("cp.async.wait_group %0;" :: "n"(n) : "memory")

// smem layout (bytes).
// fp16 tiles: 80B row stride; fp8 tiles: 48B row stride (conflict-free ldsm).
#define Q_OFF     0        // 64 x 32 half, stride 80    (5120)
#define P_OFF     5120     // 64 x 32 e4m3, stride 48    (3072)
#define K2_OFF    8192     // 3 stages x 32x32 half      (7680)
#define V_OFF     15872    // 3 stages x 256x32 e4m3 (36864); pass1 K1 stages here
#define SRED_OFF  52736    // 64 x 2 f32
#define SS_OFF    53248    // 64 f32
#define SMEM_ATTN 53504
#define K1_STAGE  10240    // 128 rows x 80B (fp16)
#define V_STAGE   12288    // 256 rows x 48B (fp8)
#define K2_STAGE  2560     // 32 rows x 80B (fp16)

// ---------------------------------------------------------------------------
// Kernel 1: fused q & k projections -> fp16
// ---------------------------------------------------------------------------
__global__ void __launch_bounds__(256) qkf_kernel(
    const float* __restrict__ x,
    const float* __restrict__ Wq, const float* __restrict__ bq,
    const float* __restrict__ Wk, const float* __restrict__ bk)
{
    int row0 = blockIdx.x * 64;
    int tid  = threadIdx.x;
    int lane = tid & 31;
    int rg   = tid >> 5;

    __shared__ __align__(16) float xs[64][68];
    __shared__ float wsq[64][33];
    __shared__ float wsk[64][33];

    float aq[8], ak[8];
#pragma unroll
    for (int r = 0; r < 8; r++) { aq[r] = 0.f; ak[r] = 0.f; }

    for (int kc = 0; kc < CC; kc += 64) {
        __syncthreads();
#pragma unroll
        for (int p = 0; p < 16; p++) {
            int idx = tid + p * 256;
            int r = idx >> 6, kk = idx & 63;
            xs[r][kk] = x[(long)(row0 + r) * CC + kc + kk];
        }
#pragma unroll
        for (int p = 0; p < 8; p++) {
            int idx = tid + p * 256;
            int kk = idx >> 5, d = idx & 31;
            wsq[kk][d] = Wq[(kc + kk) * DD + d];
            wsk[kk][d] = Wk[(kc + kk) * DD + d];
        }
        __syncthreads();
#pragma unroll
        for (int k4 = 0; k4 < 16; k4++) {
            float4 a4[8];
#pragma unroll
            for (int r = 0; r < 8; r++)
                a4[r] = *(const float4*)&xs[rg * 8 + r][k4 * 4];
#pragma unroll
            for (int qq = 0; qq < 4; qq++) {
                float bvq = wsq[k4 * 4 + qq][lane];
                float bvk = wsk[k4 * 4 + qq][lane];
#pragma unroll
                for (int r = 0; r < 8; r++) {
                    float av = ((const float*)&a4[r])[qq];
                    aq[r] += av * bvq;
                    ak[r] += av * bvk;
                }
            }
        }
    }
    float bbq = bq[lane], bbk = bk[lane];
#pragma unroll
    for (int r = 0; r < 8; r++) {
        long o = (long)(row0 + rg * 8 + r) * DD + lane;
        g_qh[o] = __float2half_rn(aq[r] + bbq);
        g_kh[o] = __float2half_rn(ak[r] + bbk);
    }
}

// ---------------------------------------------------------------------------
// Kernel 2: v = x@Wv + bv, TRANSPOSED e4m3 to g_v8t[b][c][j]
// ---------------------------------------------------------------------------
__global__ void __launch_bounds__(256, 2) v_kernel(
    const float* __restrict__ x,
    const float* __restrict__ Wv, const float* __restrict__ bv)
{
    int row0 = blockIdx.x * 64;
    int tid  = threadIdx.x;
    int lane = tid & 31, warp = tid >> 5;

    __shared__ __align__(16) float as_[64][36];
    __shared__ __align__(16) float bs[32][260];

    float acc[8][8];
#pragma unroll
    for (int r = 0; r < 8; r++)
#pragma unroll
        for (int c = 0; c < 8; c++) acc[r][c] = 0.f;

    for (int kc = 0; kc < CC; kc += 32) {
        __syncthreads();
#pragma unroll
        for (int rr = 0; rr < 8; rr++) {
            int r = warp * 8 + rr;
            as_[r][lane] = x[(long)(row0 + r) * CC + kc + lane];
        }
#pragma unroll
        for (int p = 0; p < 8; p++) {
            int idx = tid + p * 256;
            int r = idx >> 6, c4 = idx & 63;
            *(float4*)&bs[r][c4 * 4] = *(const float4*)&Wv[(long)(kc + r) * CC + c4 * 4];
        }
        __syncthreads();
#pragma unroll
        for (int k4 = 0; k4 < 8; k4++) {
            float4 a4[8];
#pragma unroll
            for (int r = 0; r < 8; r++)
                a4[r] = *(const float4*)&as_[warp * 8 + r][k4 * 4];
#pragma unroll
            for (int qq = 0; qq < 4; qq++) {
                int kk = k4 * 4 + qq;
                float bvv[8];
                *(float4*)&bvv[0] = *(const float4*)&bs[kk][lane * 4];
                *(float4*)&bvv[4] = *(const float4*)&bs[kk][128 + lane * 4];
#pragma unroll
                for (int r = 0; r < 8; r++) {
                    float av = ((const float*)&a4[r])[qq];
#pragma unroll
                    for (int c = 0; c < 8; c++)
                        acc[r][c] += av * bvv[c];
                }
            }
        }
    }
    int rowg = row0 + warp * 8;
    int bb   = rowg / NN;
    int jj   = rowg % NN;
    uint8_t* vt = g_v8t + (long)bb * CC * NN;
#pragma unroll
    for (int h = 0; h < 2; h++) {
#pragma unroll
        for (int cc = 0; cc < 4; cc++) {
            int c = h * 128 + lane * 4 + cc;
            float bias = bv[c];
            int idx = h * 4 + cc;
            uint32_t lo = (uint32_t)f2_to_e4m3x2(acc[0][idx] + bias, acc[1][idx] + bias)
                        | ((uint32_t)f2_to_e4m3x2(acc[2][idx] + bias, acc[3][idx] + bias) << 16);
            uint32_t hi = (uint32_t)f2_to_e4m3x2(acc[4][idx] + bias, acc[5][idx] + bias)
                        | ((uint32_t)f2_to_e4m3x2(acc[6][idx] + bias, acc[7][idx] + bias) << 16);
            *(uint2*)&vt[(long)c * NN + jj] = make_uint2(lo, hi);
        }
    }
}

// ---------------------------------------------------------------------------
// Kernel 3: fused attention. E/softmax in fp16 HMMA, AV in e4m3 QMMA.
//  pass 1: s_i = sum_j exp(q_i.k_j)   JT=128, cp.async 3-stage
//  pass 2: att=exp(e)/s -> gmem(f32); P'=att*4096 (e4m3); O += P'@V  JT=32
// Warp layouts: E: 4i x 2j (wi,wj); AV: 2i x 4c (avi,avc)
// ---------------------------------------------------------------------------
__global__ void __launch_bounds__(256, 2) attn_kernel(
    const float* __restrict__ x, const float* __restrict__ gamma,
    float* __restrict__ att_out, float* __restrict__ y)
{
    extern __shared__ __align__(16) char smem[];
    const uint32_t sb = smem_u32(smem);
    const int tid  = threadIdx.x;
    const int lane = tid & 31, w = tid >> 5;
    const int wi = w & 3, wj = w >> 2;
    const int avi = w & 1, avc = w >> 1;

    const int b  = blockIdx.y;
    const int i0 = blockIdx.x * 64;

    const __half*  qg  = g_qh + ((long)b * NN + i0) * DD;
    const __half*  kg  = g_kh + (long)b * NN * DD;
    const uint8_t* vtg = g_v8t + (long)b * CC * NN;

    // ---- Q tile -> smem (64 rows x 64B, stride 80B) ----
    {
        int r = tid >> 2, ch = tid & 3;
        *(uint4*)(smem + Q_OFF + r * 80 + ch * 16) =
            *(const uint4*)(qg + r * DD + ch * 8);
    }

    // prefetch K1 stage 0
    {
        uint32_t kst = sb + V_OFF;
#pragma unroll
        for (int p = 0; p < 2; p++) {
            int idx = tid + p * 256;
            int r = idx >> 2, ch = idx & 3;
            CP16(kst + r * 80 + ch * 16, kg + r * DD + ch * 8);
        }
        CP_COMMIT();
    }
    __syncthreads();

    // ---- preload Q fragments (held all kernel) ----
    uint32_t qf[2][4];
    {
        uint32_t base = sb + Q_OFF
            + (wi * 16 + (lane & 7) + ((lane >> 3) & 1) * 8) * 80
            + (lane >> 4) * 16;
        ldsm4(qf[0], base);
        ldsm4(qf[1], base + 32);
    }

    // =========================== PASS 1 ============================
    float s0 = 0.f, s1 = 0.f;
    for (int t = 0; t < 32; t++) {
        if (t + 1 < 32) {
            uint32_t kst = sb + V_OFF + ((t + 1) % 3) * K1_STAGE;
            const __half* src = kg + (t + 1) * 128 * DD;
#pragma unroll
            for (int p = 0; p < 2; p++) {
                int idx = tid + p * 256;
                int r = idx >> 2, ch = idx & 3;
                CP16(kst + r * 80 + ch * 16, src + r * DD + ch * 8);
            }
        }
        CP_COMMIT();
        CP_WAIT(1);
        __syncthreads();

        uint32_t kst = sb + V_OFF + (t % 3) * K1_STAGE;
        uint32_t bbase = kst + (wj * 64 + (lane & 7)) * 80 + (lane >> 3) * 16;
#pragma unroll
        for (int nt = 0; nt < 8; nt++) {
            uint32_t bf[4];
            ldsm4(bf, bbase + nt * 8 * 80);
            float c[4] = {0.f, 0.f, 0.f, 0.f};
            mma_f16(c, qf[0], bf[0], bf[1]);
            mma_f16(c, qf[1], bf[2], bf[3]);
            s0 += __expf(c[0]) + __expf(c[1]);
            s1 += __expf(c[2]) + __expf(c[3]);
        }
        __syncthreads();
    }
    s0 += __shfl_xor_sync(0xffffffffu, s0, 1);
    s0 += __shfl_xor_sync(0xffffffffu, s0, 2);
    s1 += __shfl_xor_sync(0xffffffffu, s1, 1);
    s1 += __shfl_xor_sync(0xffffffffu, s1, 2);
    {
        float* sred = (float*)(smem + SRED_OFF);
        if ((lane & 3) == 0) {
            int r = wi * 16 + (lane >> 2);
            sred[r * 2 + wj]       = s0;
            sred[(r + 8) * 2 + wj] = s1;
        }
    }
    __syncthreads();
    if (tid < 64) {
        float* sred = (float*)(smem + SRED_OFF);
        ((float*)(smem + SS_OFF))[tid] = 1.0f / (sred[tid * 2] + sred[tid * 2 + 1]);
    }

    // prefetch V(e4m3)+K2 stage 0
    {
        uint32_t vst = sb + V_OFF, k2t = sb + K2_OFF;
#pragma unroll
        for (int p = 0; p < 2; p++) {
            int idx = tid + p * 256;
            int c = idx >> 1, ch = idx & 1;
            CP16(vst + c * 48 + ch * 16, vtg + (long)c * NN + ch * 16);
        }
        if (tid < 128) {
            int r = tid >> 2, ch = tid & 3;
            CP16(k2t + r * 80 + ch * 16, kg + r * DD + ch * 8);
        }
        CP_COMMIT();
    }
    __syncthreads();
    const float is0 = ((const float*)(smem + SS_OFF))[wi * 16 + (lane >> 2)];
    const float is1 = ((const float*)(smem + SS_OFF))[wi * 16 + (lane >> 2) + 8];

    // =========================== PASS 2 ============================
    float acc[2][8][4];
#pragma unroll
    for (int mt = 0; mt < 2; mt++)
#pragma unroll
        for (int nt = 0; nt < 8; nt++)
#pragma unroll
            for (int u = 0; u < 4; u++) acc[mt][nt][u] = 0.f;

    float* ab = att_out ? att_out + ((long)b * NN + i0) * NN : (float*)0;
    const int er0 = wi * 16 + (lane >> 2);
    const int ec  = wj * 16 + ((lane & 3) << 1);
    const uint32_t pbaseA = sb + P_OFF
        + (avi * 32 + (lane & 7) + ((lane >> 3) & 1) * 8) * 48
        + ((lane >> 4) & 1) * 16;

    for (int t = 0; t < 128; t++) {
        const int j0 = t * 32;
        if (t + 1 < 128) {
            uint32_t vst = sb + V_OFF + ((t + 1) % 3) * V_STAGE;
            uint32_t k2t = sb + K2_OFF + ((t + 1) % 3) * K2_STAGE;
            const uint8_t* vsrc = vtg + j0 + 32;
            const __half*  ksrc = kg + (j0 + 32) * DD;
#pragma unroll
            for (int p = 0; p < 2; p++) {
                int idx = tid + p * 256;
                int c = idx >> 1, ch = idx & 1;
                CP16(vst + c * 48 + ch * 16, vsrc + (long)c * NN + ch * 16);
            }
            if (tid < 128) {
                int r = tid >> 2, ch = tid & 3;
                CP16(k2t + r * 80 + ch * 16, ksrc + r * DD + ch * 8);
            }
        }
        CP_COMMIT();
        CP_WAIT(1);
        __syncthreads();

        uint32_t vst = sb + V_OFF + (t % 3) * V_STAGE;
        uint32_t k2t = sb + K2_OFF + (t % 3) * K2_STAGE;

        // ---- E (64x32) + exp + P'(e4m3, x4096) + att(f32) ----
        uint32_t ebase = k2t + (wj * 16 + (lane & 7)) * 80 + (lane >> 3) * 16;
#pragma unroll
        for (int nt = 0; nt < 2; nt++) {
            uint32_t bf[4];
            ldsm4(bf, ebase + nt * 8 * 80);
            float c[4] = {0.f, 0.f, 0.f, 0.f};
            mma_f16(c, qf[0], bf[0], bf[1]);
            mma_f16(c, qf[1], bf[2], bf[3]);
            float a0 = __expf(c[0]) * is0, a1 = __expf(c[1]) * is0;
            float a2 = __expf(c[2]) * is1, a3 = __expf(c[3]) * is1;
            int col = ec + nt * 8;
            *(unsigned short*)(smem + P_OFF + er0 * 48 + col) =
                f2_to_e4m3x2(a0 * PSCALE, a1 * PSCALE);
            *(unsigned short*)(smem + P_OFF + (er0 + 8) * 48 + col) =
                f2_to_e4m3x2(a2 * PSCALE, a3 * PSCALE);
            if (ab) {
                *(float2*)&ab[(long)er0 * NN + j0 + col]       = make_float2(a0, a1);
                *(float2*)&ab[(long)(er0 + 8) * NN + j0 + col] = make_float2(a2, a3);
            }
        }
        __syncthreads();

        // ---- AV: O(64x256) += P'(64x32 e4m3) @ V^T(256x32 e4m3)^T ----
        uint32_t af[2][4];
        ldsm4(af[0], pbaseA);
        ldsm4(af[1], pbaseA + 16 * 48);
#pragma unroll
        for (int ntg = 0; ntg < 4; ntg++) {
            uint32_t bv[4];
            uint32_t baddr = vst
                + (avc * 64 + ntg * 16 + (lane & 7) + ((lane >> 4) & 1) * 8) * 48
                + ((lane >> 3) & 1) * 16;
            ldsm4(bv, baddr);
            mma_f8(acc[0][ntg * 2],     af[0], bv[0], bv[1]);
            mma_f8(acc[0][ntg * 2 + 1], af[0], bv[2], bv[3]);
            mma_f8(acc[1][ntg * 2],     af[1], bv[0], bv[1]);
            mma_f8(acc[1][ntg * 2 + 1], af[1], bv[2], bv[3]);
        }
    }

    // ---- epilogue: y = acc*(gamma/PSCALE) + x ----
    const float g = gamma[0] * (1.0f / PSCALE);
    const float* xb = x + ((long)b * NN + i0) * CC;
    float* yb = y + ((long)b * NN + i0) * CC;
#pragma unroll
    for (int mt = 0; mt < 2; mt++) {
        int r0 = avi * 32 + mt * 16 + (lane >> 2);
#pragma unroll
        for (int nt = 0; nt < 8; nt++) {
            int c = avc * 64 + nt * 8 + ((lane & 3) << 1);
            float2 x0 = *(const float2*)&xb[(long)r0 * CC + c];
            float2 x1 = *(const float2*)&xb[(long)(r0 + 8) * CC + c];
            float2 o0, o1;
            o0.x = acc[mt][nt][0] * g + x0.x;  o0.y = acc[mt][nt][1] * g + x0.y;
            o1.x = acc[mt][nt][2] * g + x1.x;  o1.y = acc[mt][nt][3] * g + x1.y;
            *(float2*)&yb[(long)r0 * CC + c]       = o0;
            *(float2*)&yb[(long)(r0 + 8) * CC + c] = o1;
        }
    }
}

// ---------------------------------------------------------------------------
extern "C" void kernel_launch(void* const* d_in, const int* in_sizes, int n_in,
                              void* d_out, int out_size)
{
    const float* x     = (const float*)d_in[0];
    const float* Wq    = (const float*)d_in[1];
    const float* bq    = (const float*)d_in[2];
    const float* Wk    = (const float*)d_in[3];
    const float* bk    = (const float*)d_in[4];
    const float* Wv    = (const float*)d_in[5];
    const float* bv    = (const float*)d_in[6];
    const float* gamma = (const float*)d_in[7];
    float* y = (float*)d_out;

    const long ATT_E = (long)BN * NN * NN;
    float* att_out = 0;
    if ((long)out_size == (long)OUT_E + ATT_E) att_out = y + OUT_E;

    cudaFuncSetAttribute(attn_kernel, cudaFuncAttributeMaxDynamicSharedMemorySize,
                         SMEM_ATTN);

    qkf_kernel<<<BN * NN / 64, 256>>>(x, Wq, bq, Wk, bk);
    v_kernel<<<BN * NN / 64, 256>>>(x, Wv, bv);
    attn_kernel<<<dim3(NN / 64, BN), 256, SMEM_ATTN>>>(x, gamma, att_out, y);
}